// round 1
// baseline (speedup 1.0000x reference)
#include <cuda_runtime.h>
#include <math.h>

// Problem dims
#define BB   256
#define SS   16
#define HH   8
#define HSD  128
#define DD   1024
#define MM   1024
#define BSR  (BB*SS)          // 4096 rows for the big GEMMs
#define BSMN ((size_t)BSR*MM) // 4,194,304 elements per output tensor

// Scratch (no allocs allowed -> __device__ globals)
// g_x layout: [4][B][M] = x_emb, wx_f, wx_i, wx_o
__device__ float g_x[4 * BB * MM];     // 4 MB
__device__ float g_mp[BSR * MM];       // 16 MB: memory_proposal pre-W_g (m_state + attended)

__device__ __forceinline__ float sigf(float x) { return 1.0f / (1.0f + expf(-x)); }

// ---------------------------------------------------------------------------
// Kernel A: X[z] = inputs @ W[z] (+ b_emb for z==0), z in {emb, wf, wi, wo}
// Tiles: BM=64, BN=64, BK=16, 256 threads, 4x4 per thread.
// ---------------------------------------------------------------------------
__global__ __launch_bounds__(256) void gemm_x_kernel(
    const float* __restrict__ inp,  const float* __restrict__ Wemb,
    const float* __restrict__ Wwf,  const float* __restrict__ Wwi,
    const float* __restrict__ Wwo,  const float* __restrict__ bemb)
{
    __shared__ __align__(16) float sA[16][64];   // transposed: sA[k][m]
    __shared__ __align__(16) float sB[16][64];

    const int z = blockIdx.z;
    const float* W = (z == 0) ? Wemb : (z == 1) ? Wwf : (z == 2) ? Wwi : Wwo;

    const int tid  = threadIdx.x;
    const int tx   = tid & 15;          // 0..15 -> col group
    const int ty   = tid >> 4;          // 0..15 -> row group
    const int row0 = blockIdx.y * 64;
    const int col0 = blockIdx.x * 64;

    const int arow = tid >> 2;          // 0..63
    const int acol = (tid & 3) * 4;     // 0,4,8,12
    const int brow = tid >> 4;          // 0..15
    const int bcol = (tid & 15) * 4;

    float acc[4][4] = {};

    for (int kt = 0; kt < DD; kt += 16) {
        float4 av = *(const float4*)&inp[(size_t)(row0 + arow) * DD + kt + acol];
        sA[acol + 0][arow] = av.x; sA[acol + 1][arow] = av.y;
        sA[acol + 2][arow] = av.z; sA[acol + 3][arow] = av.w;
        *(float4*)&sB[brow][bcol] =
            *(const float4*)&W[(size_t)(kt + brow) * MM + col0 + bcol];
        __syncthreads();

        #pragma unroll
        for (int kk = 0; kk < 16; kk++) {
            float a[4], b[4];
            *(float4*)a = *(const float4*)&sA[kk][ty * 4];
            *(float4*)b = *(const float4*)&sB[kk][tx * 4];
            #pragma unroll
            for (int i = 0; i < 4; i++)
                #pragma unroll
                for (int j = 0; j < 4; j++)
                    acc[i][j] += a[i] * b[j];
        }
        __syncthreads();
    }

    float bias[4] = {0.f, 0.f, 0.f, 0.f};
    if (z == 0) *(float4*)bias = *(const float4*)&bemb[col0 + tx * 4];

    float* outp = g_x + (size_t)z * BB * MM;
    #pragma unroll
    for (int i = 0; i < 4; i++) {
        float v[4];
        #pragma unroll
        for (int j = 0; j < 4; j++) v[j] = acc[i][j] + bias[j];
        *(float4*)&outp[(size_t)(row0 + ty * 4 + i) * MM + col0 + tx * 4] = *(float4*)v;
    }
}

// ---------------------------------------------------------------------------
// Kernel B: attention per (b, h). kv rows 0..15 == q rows (m_state head slice),
// kv row 16 = dense_inputs head slice. Writes g_mp = m_state + attended.
// ---------------------------------------------------------------------------
__global__ __launch_bounds__(256) void attn_kernel(const float* __restrict__ mstate)
{
    __shared__ __align__(16) float kv[17][HSD];
    __shared__ float sc[16][20];

    const int bh  = blockIdx.x;
    const int b   = bh >> 3;
    const int h   = bh & 7;
    const int tid = threadIdx.x;

    const float* mb = mstate + (size_t)b * SS * MM + h * HSD;

    for (int i = tid; i < 17 * HSD; i += 256) {
        int t = i >> 7, d = i & 127;
        kv[t][d] = (t < SS) ? mb[(size_t)t * MM + d]
                            : g_x[(size_t)b * MM + h * HSD + d];
    }
    __syncthreads();

    const int wid = tid >> 5, lane = tid & 31;
    for (int s = wid; s < 16; s += 8) {
        for (int t = 0; t < 17; t++) {
            float sum = 0.f;
            #pragma unroll
            for (int d = lane; d < HSD; d += 32) sum += kv[s][d] * kv[t][d];
            #pragma unroll
            for (int o = 16; o; o >>= 1) sum += __shfl_xor_sync(0xffffffffu, sum, o);
            if (lane == 0) sc[s][t] = sum * 0.08838834764831845f;  // 1/sqrt(128)
        }
    }
    __syncthreads();

    if (tid < 16) {
        float mx = sc[tid][0];
        for (int t = 1; t < 17; t++) mx = fmaxf(mx, sc[tid][t]);
        float sum = 0.f;
        for (int t = 0; t < 17; t++) { float e = expf(sc[tid][t] - mx); sc[tid][t] = e; sum += e; }
        float inv = 1.0f / sum;
        for (int t = 0; t < 17; t++) sc[tid][t] *= inv;
    }
    __syncthreads();

    for (int i = tid; i < SS * HSD; i += 256) {
        int s = i >> 7, d = i & 127;
        float acc = 0.f;
        #pragma unroll
        for (int t = 0; t < 17; t++) acc += sc[s][t] * kv[t][d];
        g_mp[((size_t)b * SS + s) * MM + h * HSD + d] = kv[s][d] + acc;
    }
}

// ---------------------------------------------------------------------------
// Kernel C: fused 4-way GEMM + full gate epilogue.
//   acc_g = mp @ W_g ; acc_f/i/o = h_state @ W_u{f,i,o}
// Epilogue: all elementwise math, writes new_memories and new_hidden.
// Tiles: BM=64, BN=64, BK=16, 256 threads, 4x4 per thread per accumulator.
// ---------------------------------------------------------------------------
__global__ __launch_bounds__(256, 2) void fused_gate_kernel(
    const float* __restrict__ hstate, const float* __restrict__ mstate,
    const float* __restrict__ Wg,  const float* __restrict__ bg,
    const float* __restrict__ Wuf, const float* __restrict__ buf_,
    const float* __restrict__ Wui, const float* __restrict__ bui,
    const float* __restrict__ Wuo, const float* __restrict__ buo,
    float* __restrict__ out)
{
    __shared__ __align__(16) float sAm[16][64];  // mp, transposed
    __shared__ __align__(16) float sAh[16][64];  // h_state, transposed
    __shared__ __align__(16) float sBg[16][64];
    __shared__ __align__(16) float sBf[16][64];
    __shared__ __align__(16) float sBi[16][64];
    __shared__ __align__(16) float sBo[16][64];

    const int tid  = threadIdx.x;
    const int tx   = tid & 15;
    const int ty   = tid >> 4;
    const int row0 = blockIdx.y * 64;
    const int col0 = blockIdx.x * 64;

    const int arow = tid >> 2;
    const int acol = (tid & 3) * 4;
    const int brow = tid >> 4;
    const int bcol = (tid & 15) * 4;

    float ag[4][4] = {}, af[4][4] = {}, ai[4][4] = {}, ao[4][4] = {};

    for (int kt = 0; kt < MM; kt += 16) {
        float4 v;
        v = *(const float4*)&g_mp[(size_t)(row0 + arow) * MM + kt + acol];
        sAm[acol + 0][arow] = v.x; sAm[acol + 1][arow] = v.y;
        sAm[acol + 2][arow] = v.z; sAm[acol + 3][arow] = v.w;
        v = *(const float4*)&hstate[(size_t)(row0 + arow) * MM + kt + acol];
        sAh[acol + 0][arow] = v.x; sAh[acol + 1][arow] = v.y;
        sAh[acol + 2][arow] = v.z; sAh[acol + 3][arow] = v.w;

        const size_t boff = (size_t)(kt + brow) * MM + col0 + bcol;
        *(float4*)&sBg[brow][bcol] = *(const float4*)&Wg[boff];
        *(float4*)&sBf[brow][bcol] = *(const float4*)&Wuf[boff];
        *(float4*)&sBi[brow][bcol] = *(const float4*)&Wui[boff];
        *(float4*)&sBo[brow][bcol] = *(const float4*)&Wuo[boff];
        __syncthreads();

        #pragma unroll
        for (int kk = 0; kk < 16; kk++) {
            float am[4], ah[4], vg[4], vf[4], vi[4], vo[4];
            *(float4*)am = *(const float4*)&sAm[kk][ty * 4];
            *(float4*)ah = *(const float4*)&sAh[kk][ty * 4];
            *(float4*)vg = *(const float4*)&sBg[kk][tx * 4];
            *(float4*)vf = *(const float4*)&sBf[kk][tx * 4];
            *(float4*)vi = *(const float4*)&sBi[kk][tx * 4];
            *(float4*)vo = *(const float4*)&sBo[kk][tx * 4];
            #pragma unroll
            for (int i = 0; i < 4; i++)
                #pragma unroll
                for (int j = 0; j < 4; j++) {
                    ag[i][j] += am[i] * vg[j];
                    af[i][j] += ah[i] * vf[j];
                    ai[i][j] += ah[i] * vi[j];
                    ao[i][j] += ah[i] * vo[j];
                }
        }
        __syncthreads();
    }

    // Epilogue: full elementwise fusion
    const int nc = col0 + tx * 4;
    float bgv[4], bfv[4], biv[4], bov[4];
    *(float4*)bgv = *(const float4*)&bg[nc];
    *(float4*)bfv = *(const float4*)&buf_[nc];
    *(float4*)biv = *(const float4*)&bui[nc];
    *(float4*)bov = *(const float4*)&buo[nc];

    #pragma unroll
    for (int i = 0; i < 4; i++) {
        const int r = row0 + ty * 4 + i;
        const int bidx = r >> 4;                      // batch index (S = 16)
        const size_t base = (size_t)r * MM + nc;

        float mv[4], mpv[4], wf[4], wi[4], wo[4];
        *(float4*)mv  = *(const float4*)&mstate[base];
        *(float4*)mpv = *(const float4*)&g_mp[base];
        *(float4*)wf  = *(const float4*)&g_x[(size_t)1 * BB * MM + (size_t)bidx * MM + nc];
        *(float4*)wi  = *(const float4*)&g_x[(size_t)2 * BB * MM + (size_t)bidx * MM + nc];
        *(float4*)wo  = *(const float4*)&g_x[(size_t)3 * BB * MM + (size_t)bidx * MM + nc];

        float nm[4], nh[4];
        #pragma unroll
        for (int j = 0; j < 4; j++) {
            float mpf  = ag[i][j] + bgv[j] + mpv[j];               // (mp@Wg + bg) + mp
            float fgt  = sigf(af[i][j] + bfv[j] + wf[j]);          // forget gate
            float igt  = sigf(ai[i][j] + biv[j] + wi[j]);          // input gate (1st sigmoid)
            float ogt  = sigf(ao[i][j] + bov[j] + wo[j]);          // output gate (1st sigmoid)
            nm[j] = sigf(mv[j] * fgt + 1.0f) + mpf * sigf(igt);    // FORGET_BIAS = 1.0
            nh[j] = tanhf(mv[j]) * sigf(ogt);
        }
        *(float4*)&out[base]        = *(float4*)nm;
        *(float4*)&out[BSMN + base] = *(float4*)nh;
    }
}

// ---------------------------------------------------------------------------
extern "C" void kernel_launch(void* const* d_in, const int* in_sizes, int n_in,
                              void* d_out, int out_size)
{
    const float* inputs  = (const float*)d_in[0];
    const float* h_state = (const float*)d_in[1];
    const float* m_state = (const float*)d_in[2];
    const float* W_emb   = (const float*)d_in[3];
    const float* b_emb   = (const float*)d_in[4];
    const float* W_g     = (const float*)d_in[5];
    const float* b_g     = (const float*)d_in[6];
    const float* W_wf    = (const float*)d_in[7];
    const float* W_wi    = (const float*)d_in[8];
    const float* W_wo    = (const float*)d_in[9];
    const float* W_uf    = (const float*)d_in[10];
    const float* b_uf    = (const float*)d_in[11];
    const float* W_ui    = (const float*)d_in[12];
    const float* b_ui    = (const float*)d_in[13];
    const float* W_uo    = (const float*)d_in[14];
    const float* b_uo    = (const float*)d_in[15];
    float* out = (float*)d_out;

    // 1) Input projections: x_emb, wx_f, wx_i, wx_o
    gemm_x_kernel<<<dim3(16, 4, 4), 256>>>(inputs, W_emb, W_wf, W_wi, W_wo, b_emb);
    // 2) Attention -> g_mp = m_state + attended
    attn_kernel<<<BB * HH, 256>>>(m_state);
    // 3) Fused 4-way GEMM + gates -> both outputs
    fused_gate_kernel<<<dim3(16, 64), 256>>>(h_state, m_state,
                                             W_g, b_g, W_uf, b_uf,
                                             W_ui, b_ui, W_uo, b_uo, out);
}

// round 2
// speedup vs baseline: 2.0870x; 2.0870x over previous
#include <cuda_runtime.h>
#include <math.h>

// Problem dims
#define BB   256
#define SS   16
#define HH   8
#define HSD  128
#define DD   1024
#define MM   1024
#define BSR  (BB*SS)          // 4096 rows for the big GEMMs
#define BSMN ((size_t)BSR*MM)

// Scratch (__device__ globals; no allocs allowed)
__device__ float g_x[4 * BB * MM];   // [4][B][M]: x_emb, wx_f, wx_i, wx_o
__device__ float g_mp[BSR * MM];     // m_state + attended (pre-W_g proposal)

__device__ __forceinline__ float sigf(float x) { return 1.0f / (1.0f + expf(-x)); }

__device__ __forceinline__ unsigned f2t(float f) {
    unsigned u; asm("cvt.rna.tf32.f32 %0, %1;" : "=r"(u) : "f"(f)); return u;
}

__device__ __forceinline__ void mma8(float* c, const unsigned* a, const unsigned* b) {
    asm volatile(
        "mma.sync.aligned.m16n8k8.row.col.f32.tf32.tf32.f32 "
        "{%0,%1,%2,%3}, {%4,%5,%6,%7}, {%8,%9}, {%0,%1,%2,%3};"
        : "+f"(c[0]), "+f"(c[1]), "+f"(c[2]), "+f"(c[3])
        : "r"(a[0]), "r"(a[1]), "r"(a[2]), "r"(a[3]), "r"(b[0]), "r"(b[1]));
}

// A smem: [m][k] stride 20 (conflict-free frag loads); B smem: [k][n] stride 72.
#define ASTR 20
#define BSTR 72

// ---------------------------------------------------------------------------
// Kernel A: X[z] = inputs @ W[z] (+ b_emb for z==0) via tf32 mma.
// BM=64, BN=64, BK=16, 256 threads, warp tile 32x16.
// ---------------------------------------------------------------------------
__global__ __launch_bounds__(256) void gemm_x_mma(
    const float* __restrict__ inp,  const float* __restrict__ Wemb,
    const float* __restrict__ Wwf,  const float* __restrict__ Wwi,
    const float* __restrict__ Wwo,  const float* __restrict__ bemb)
{
    __shared__ unsigned sA[64 * ASTR];
    __shared__ unsigned sB[16 * BSTR];

    const int z = blockIdx.z;
    const float* W = (z == 0) ? Wemb : (z == 1) ? Wwf : (z == 2) ? Wwi : Wwo;

    const int tid  = threadIdx.x;
    const int lane = tid & 31, wid = tid >> 5;
    const int wr = wid >> 2, wc = wid & 3;
    const int row0 = blockIdx.y * 64, col0 = blockIdx.x * 64;

    const int lar = tid >> 2;          // A row 0..63
    const int lak = (tid & 3) * 4;     // A k 0,4,8,12
    const int lbk = tid >> 4;          // B k 0..15
    const int lbn = (tid & 15) * 4;    // B n offset

    const int kq = lane & 3, gq = lane >> 2;

    float4 fa, fb;
    fa = *(const float4*)&inp[(size_t)(row0 + lar) * DD + lak];
    fb = *(const float4*)&W[(size_t)lbk * MM + col0 + lbn];

    float acc[2][2][4] = {};

    for (int kt = 0; kt < DD / 16; kt++) {
        unsigned* dA = &sA[lar * ASTR + lak];
        dA[0] = f2t(fa.x); dA[1] = f2t(fa.y); dA[2] = f2t(fa.z); dA[3] = f2t(fa.w);
        uint4 v = make_uint4(f2t(fb.x), f2t(fb.y), f2t(fb.z), f2t(fb.w));
        *(uint4*)&sB[lbk * BSTR + lbn] = v;
        __syncthreads();

        if (kt < DD / 16 - 1) {
            int k0 = (kt + 1) * 16;
            fa = *(const float4*)&inp[(size_t)(row0 + lar) * DD + k0 + lak];
            fb = *(const float4*)&W[(size_t)(k0 + lbk) * MM + col0 + lbn];
        }

        #pragma unroll
        for (int ks = 0; ks < 2; ks++) {
            const int k8 = ks * 8;
            unsigned am[2][4];
            #pragma unroll
            for (int mt = 0; mt < 2; mt++) {
                const int rb = (wr * 32 + mt * 16 + gq) * ASTR + k8 + kq;
                am[mt][0] = sA[rb];            am[mt][1] = sA[rb + 8 * ASTR];
                am[mt][2] = sA[rb + 4];        am[mt][3] = sA[rb + 8 * ASTR + 4];
            }
            #pragma unroll
            for (int nt = 0; nt < 2; nt++) {
                const int nb = wc * 16 + nt * 8 + gq;
                unsigned b[2];
                b[0] = sB[(k8 + kq) * BSTR + nb];
                b[1] = sB[(k8 + kq + 4) * BSTR + nb];
                mma8(acc[0][nt], am[0], b);
                mma8(acc[1][nt], am[1], b);
            }
        }
        __syncthreads();
    }

    float* outp = g_x + (size_t)z * BB * MM;
    #pragma unroll
    for (int nt = 0; nt < 2; nt++) {
        const int c = col0 + wc * 16 + nt * 8 + 2 * kq;
        float2 bv = make_float2(0.f, 0.f);
        if (z == 0) bv = *(const float2*)&bemb[c];
        #pragma unroll
        for (int mt = 0; mt < 2; mt++) {
            #pragma unroll
            for (int h = 0; h < 2; h++) {
                const int r = row0 + wr * 32 + mt * 16 + gq + h * 8;
                float2 o;
                o.x = acc[mt][nt][2 * h + 0] + bv.x;
                o.y = acc[mt][nt][2 * h + 1] + bv.y;
                *(float2*)&outp[(size_t)r * MM + c] = o;
            }
        }
    }
}

// ---------------------------------------------------------------------------
// Kernel B: attention per (b, h); writes g_mp = m_state + attended.
// ---------------------------------------------------------------------------
__global__ __launch_bounds__(256) void attn_kernel(const float* __restrict__ mstate)
{
    __shared__ __align__(16) float kv[17][HSD];
    __shared__ float sc[16][20];

    const int bh  = blockIdx.x;
    const int b   = bh >> 3;
    const int h   = bh & 7;
    const int tid = threadIdx.x;

    const float* mb = mstate + (size_t)b * SS * MM + h * HSD;

    for (int i = tid; i < 17 * HSD; i += 256) {
        int t = i >> 7, d = i & 127;
        kv[t][d] = (t < SS) ? mb[(size_t)t * MM + d]
                            : g_x[(size_t)b * MM + h * HSD + d];
    }
    __syncthreads();

    const int wid = tid >> 5, lane = tid & 31;
    for (int s = wid; s < 16; s += 8) {
        for (int t = 0; t < 17; t++) {
            float sum = 0.f;
            #pragma unroll
            for (int d = lane; d < HSD; d += 32) sum += kv[s][d] * kv[t][d];
            #pragma unroll
            for (int o = 16; o; o >>= 1) sum += __shfl_xor_sync(0xffffffffu, sum, o);
            if (lane == 0) sc[s][t] = sum * 0.08838834764831845f;
        }
    }
    __syncthreads();

    if (tid < 16) {
        float mx = sc[tid][0];
        for (int t = 1; t < 17; t++) mx = fmaxf(mx, sc[tid][t]);
        float sum = 0.f;
        for (int t = 0; t < 17; t++) { float e = expf(sc[tid][t] - mx); sc[tid][t] = e; sum += e; }
        float inv = 1.0f / sum;
        for (int t = 0; t < 17; t++) sc[tid][t] *= inv;
    }
    __syncthreads();

    for (int i = tid; i < SS * HSD; i += 256) {
        int s = i >> 7, d = i & 127;
        float acc = 0.f;
        #pragma unroll
        for (int t = 0; t < 17; t++) acc += sc[s][t] * kv[t][d];
        g_mp[((size_t)b * SS + s) * MM + h * HSD + d] = kv[s][d] + acc;
    }
}

// ---------------------------------------------------------------------------
// Kernel C: fused 4-way tf32-mma GEMM + full gate epilogue.
//   acc0 = mp @ W_g ; acc1/2/3 = h_state @ W_u{f,i,o}
// BM=64, BN=64, BK=16, 256 threads (8 warps, warp tile 32x16).
// ---------------------------------------------------------------------------
__global__ __launch_bounds__(256) void fused_gate_mma(
    const float* __restrict__ hstate, const float* __restrict__ mstate,
    const float* __restrict__ Wg,  const float* __restrict__ bg,
    const float* __restrict__ Wuf, const float* __restrict__ buf_,
    const float* __restrict__ Wui, const float* __restrict__ bui,
    const float* __restrict__ Wuo, const float* __restrict__ buo,
    float* __restrict__ out)
{
    __shared__ unsigned sAm[64 * ASTR];      // mp tile
    __shared__ unsigned sAh[64 * ASTR];      // h_state tile
    __shared__ unsigned sB[4][16 * BSTR];    // Wg, Wuf, Wui, Wuo tiles

    const int tid  = threadIdx.x;
    const int lane = tid & 31, wid = tid >> 5;
    const int wr = wid >> 2, wc = wid & 3;
    const int row0 = blockIdx.y * 64, col0 = blockIdx.x * 64;

    const int lar = tid >> 2;
    const int lak = (tid & 3) * 4;
    const int lbk = tid >> 4;
    const int lbn = (tid & 15) * 4;
    const int kq = lane & 3, gq = lane >> 2;

    const float* Bp0 = Wg;  const float* Bp1 = Wuf;
    const float* Bp2 = Wui; const float* Bp3 = Wuo;

    float4 fa0, fa1, fb0, fb1, fb2, fb3;
    {
        const size_t aoff = (size_t)(row0 + lar) * MM + lak;
        fa0 = *(const float4*)&g_mp[aoff];
        fa1 = *(const float4*)&hstate[aoff];
        const size_t boff = (size_t)lbk * MM + col0 + lbn;
        fb0 = *(const float4*)&Bp0[boff];
        fb1 = *(const float4*)&Bp1[boff];
        fb2 = *(const float4*)&Bp2[boff];
        fb3 = *(const float4*)&Bp3[boff];
    }

    float acc[4][2][2][4] = {};   // [gemm][mt][nt][reg]

    for (int kt = 0; kt < MM / 16; kt++) {
        {
            unsigned* d = &sAm[lar * ASTR + lak];
            d[0] = f2t(fa0.x); d[1] = f2t(fa0.y); d[2] = f2t(fa0.z); d[3] = f2t(fa0.w);
            d = &sAh[lar * ASTR + lak];
            d[0] = f2t(fa1.x); d[1] = f2t(fa1.y); d[2] = f2t(fa1.z); d[3] = f2t(fa1.w);
            const int bo = lbk * BSTR + lbn;
            *(uint4*)&sB[0][bo] = make_uint4(f2t(fb0.x), f2t(fb0.y), f2t(fb0.z), f2t(fb0.w));
            *(uint4*)&sB[1][bo] = make_uint4(f2t(fb1.x), f2t(fb1.y), f2t(fb1.z), f2t(fb1.w));
            *(uint4*)&sB[2][bo] = make_uint4(f2t(fb2.x), f2t(fb2.y), f2t(fb2.z), f2t(fb2.w));
            *(uint4*)&sB[3][bo] = make_uint4(f2t(fb3.x), f2t(fb3.y), f2t(fb3.z), f2t(fb3.w));
        }
        __syncthreads();

        if (kt < MM / 16 - 1) {
            const int k0 = (kt + 1) * 16;
            const size_t aoff = (size_t)(row0 + lar) * MM + k0 + lak;
            fa0 = *(const float4*)&g_mp[aoff];
            fa1 = *(const float4*)&hstate[aoff];
            const size_t boff = (size_t)(k0 + lbk) * MM + col0 + lbn;
            fb0 = *(const float4*)&Bp0[boff];
            fb1 = *(const float4*)&Bp1[boff];
            fb2 = *(const float4*)&Bp2[boff];
            fb3 = *(const float4*)&Bp3[boff];
        }

        #pragma unroll
        for (int ks = 0; ks < 2; ks++) {
            const int k8 = ks * 8;
            unsigned am[2][4], ah[2][4];
            #pragma unroll
            for (int mt = 0; mt < 2; mt++) {
                const int rb = (wr * 32 + mt * 16 + gq) * ASTR + k8 + kq;
                am[mt][0] = sAm[rb];         am[mt][1] = sAm[rb + 8 * ASTR];
                am[mt][2] = sAm[rb + 4];     am[mt][3] = sAm[rb + 8 * ASTR + 4];
                ah[mt][0] = sAh[rb];         ah[mt][1] = sAh[rb + 8 * ASTR];
                ah[mt][2] = sAh[rb + 4];     ah[mt][3] = sAh[rb + 8 * ASTR + 4];
            }
            #pragma unroll
            for (int nt = 0; nt < 2; nt++) {
                const int nb = wc * 16 + nt * 8 + gq;
                #pragma unroll
                for (int g = 0; g < 4; g++) {
                    unsigned b[2];
                    b[0] = sB[g][(k8 + kq) * BSTR + nb];
                    b[1] = sB[g][(k8 + kq + 4) * BSTR + nb];
                    if (g == 0) {
                        mma8(acc[0][0][nt], am[0], b);
                        mma8(acc[0][1][nt], am[1], b);
                    } else {
                        mma8(acc[g][0][nt], ah[0], b);
                        mma8(acc[g][1][nt], ah[1], b);
                    }
                }
            }
        }
        __syncthreads();
    }

    // -------- fused gate epilogue --------
    #pragma unroll
    for (int nt = 0; nt < 2; nt++) {
        const int c = col0 + wc * 16 + nt * 8 + 2 * kq;
        const float2 bgv = *(const float2*)&bg[c];
        const float2 bfv = *(const float2*)&buf_[c];
        const float2 biv = *(const float2*)&bui[c];
        const float2 bov = *(const float2*)&buo[c];
        #pragma unroll
        for (int mt = 0; mt < 2; mt++) {
            #pragma unroll
            for (int h = 0; h < 2; h++) {
                const int r = row0 + wr * 32 + mt * 16 + gq + h * 8;
                const int bidx = r >> 4;
                const size_t base = (size_t)r * MM + c;
                const float2 mv  = *(const float2*)&mstate[base];
                const float2 mpv = *(const float2*)&g_mp[base];
                const float2 wfv = *(const float2*)&g_x[(size_t)1 * BB * MM + (size_t)bidx * MM + c];
                const float2 wiv = *(const float2*)&g_x[(size_t)2 * BB * MM + (size_t)bidx * MM + c];
                const float2 wov = *(const float2*)&g_x[(size_t)3 * BB * MM + (size_t)bidx * MM + c];

                float2 nm, nh;
                {
                    const float cgv = acc[0][mt][nt][2 * h + 0];
                    const float cfv = acc[1][mt][nt][2 * h + 0];
                    const float civ = acc[2][mt][nt][2 * h + 0];
                    const float cov = acc[3][mt][nt][2 * h + 0];
                    const float mpf = cgv + bgv.x + mpv.x;
                    const float fgt = sigf(cfv + bfv.x + wfv.x);
                    const float igt = sigf(civ + biv.x + wiv.x);
                    const float ogt = sigf(cov + bov.x + wov.x);
                    nm.x = sigf(mv.x * fgt + 1.0f) + mpf * sigf(igt);
                    nh.x = tanhf(mv.x) * sigf(ogt);
                }
                {
                    const float cgv = acc[0][mt][nt][2 * h + 1];
                    const float cfv = acc[1][mt][nt][2 * h + 1];
                    const float civ = acc[2][mt][nt][2 * h + 1];
                    const float cov = acc[3][mt][nt][2 * h + 1];
                    const float mpf = cgv + bgv.y + mpv.y;
                    const float fgt = sigf(cfv + bfv.y + wfv.y);
                    const float igt = sigf(civ + biv.y + wiv.y);
                    const float ogt = sigf(cov + bov.y + wov.y);
                    nm.y = sigf(mv.y * fgt + 1.0f) + mpf * sigf(igt);
                    nh.y = tanhf(mv.y) * sigf(ogt);
                }
                *(float2*)&out[base]        = nm;
                *(float2*)&out[BSMN + base] = nh;
            }
        }
    }
}

// ---------------------------------------------------------------------------
extern "C" void kernel_launch(void* const* d_in, const int* in_sizes, int n_in,
                              void* d_out, int out_size)
{
    const float* inputs  = (const float*)d_in[0];
    const float* h_state = (const float*)d_in[1];
    const float* m_state = (const float*)d_in[2];
    const float* W_emb   = (const float*)d_in[3];
    const float* b_emb   = (const float*)d_in[4];
    const float* W_g     = (const float*)d_in[5];
    const float* b_g     = (const float*)d_in[6];
    const float* W_wf    = (const float*)d_in[7];
    const float* W_wi    = (const float*)d_in[8];
    const float* W_wo    = (const float*)d_in[9];
    const float* W_uf    = (const float*)d_in[10];
    const float* b_uf    = (const float*)d_in[11];
    const float* W_ui    = (const float*)d_in[12];
    const float* b_ui    = (const float*)d_in[13];
    const float* W_uo    = (const float*)d_in[14];
    const float* b_uo    = (const float*)d_in[15];
    float* out = (float*)d_out;

    gemm_x_mma<<<dim3(16, 4, 4), 256>>>(inputs, W_emb, W_wf, W_wi, W_wo, b_emb);
    attn_kernel<<<BB * HH, 256>>>(m_state);
    fused_gate_mma<<<dim3(16, 64), 256>>>(h_state, m_state,
                                          W_g, b_g, W_uf, b_uf,
                                          W_ui, b_ui, W_uo, b_uo, out);
}

// round 3
// speedup vs baseline: 2.1574x; 1.0337x over previous
#include <cuda_runtime.h>
#include <math.h>

// Problem dims
#define BB   256
#define SS   16
#define HH   8
#define HSD  128
#define DD   1024
#define MM   1024
#define BSR  (BB*SS)
#define BSMN ((size_t)BSR*MM)

// Scratch (__device__ globals; no allocs allowed)
__device__ float g_x[4 * BB * MM];   // [4][B][M]: x_emb, wx_f, wx_i, wx_o
__device__ float g_mp[BSR * MM];     // m_state + attended

__device__ __forceinline__ float sigf(float x) { return 1.0f / (1.0f + expf(-x)); }

// Feed raw fp32 bits to tf32 MMA (HW reads top 19 bits => RZ-truncated tf32).
__device__ __forceinline__ void mma8(float* c, const unsigned* a, const unsigned* b) {
    asm volatile(
        "mma.sync.aligned.m16n8k8.row.col.f32.tf32.tf32.f32 "
        "{%0,%1,%2,%3}, {%4,%5,%6,%7}, {%8,%9}, {%0,%1,%2,%3};"
        : "+f"(c[0]), "+f"(c[1]), "+f"(c[2]), "+f"(c[3])
        : "r"(a[0]), "r"(a[1]), "r"(a[2]), "r"(a[3]), "r"(b[0]), "r"(b[1]));
}

__device__ __forceinline__ void cpa16(void* dst, const void* src) {
    unsigned s = (unsigned)__cvta_generic_to_shared(dst);
    asm volatile("cp.async.cg.shared.global [%0], [%1], 16;" :: "r"(s), "l"(src));
}
__device__ __forceinline__ void cpa_commit() {
    asm volatile("cp.async.commit_group;");
}
__device__ __forceinline__ void cpa_wait1() {
    asm volatile("cp.async.wait_group 1;");
}
__device__ __forceinline__ void cpa_wait0() {
    asm volatile("cp.async.wait_group 0;");
}

// A smem: [m][k] stride 20; B smem: [k][n] stride 72 (both conflict-free).
#define ASTR 20
#define BSTR 72
#define AW   (64 * ASTR)   // words per A tile stage
#define BW   (16 * BSTR)   // words per B tile stage

// ---------------------------------------------------------------------------
// Kernel A: X[z] = inputs @ W[z] (+ b_emb for z==0). tf32 mma, 2-stage cp.async.
// ---------------------------------------------------------------------------
__global__ __launch_bounds__(256) void gemm_x_mma(
    const float* __restrict__ inp,  const float* __restrict__ Wemb,
    const float* __restrict__ Wwf,  const float* __restrict__ Wwi,
    const float* __restrict__ Wwo,  const float* __restrict__ bemb)
{
    __shared__ unsigned sA[2][AW];
    __shared__ unsigned sB[2][BW];

    const int z = blockIdx.z;
    const float* W = (z == 0) ? Wemb : (z == 1) ? Wwf : (z == 2) ? Wwi : Wwo;

    const int tid  = threadIdx.x;
    const int lane = tid & 31, wid = tid >> 5;
    const int wr = wid >> 2, wc = wid & 3;
    const int row0 = blockIdx.y * 64, col0 = blockIdx.x * 64;

    const int lar = tid >> 2;          // A row 0..63
    const int lak = (tid & 3) * 4;     // A k 0,4,8,12
    const int lbk = tid >> 4;          // B k 0..15
    const int lbn = (tid & 15) * 4;    // B n offset
    const int kq = lane & 3, gq = lane >> 2;

    // stage 0 loads
    cpa16(&sA[0][lar * ASTR + lak], &inp[(size_t)(row0 + lar) * DD + lak]);
    cpa16(&sB[0][lbk * BSTR + lbn], &W[(size_t)lbk * MM + col0 + lbn]);
    cpa_commit();

    float acc[2][2][4] = {};
    int buf = 0;

    for (int kt = 0; kt < DD / 16; kt++) {
        if (kt + 1 < DD / 16) {
            const int k0 = (kt + 1) * 16;
            cpa16(&sA[buf ^ 1][lar * ASTR + lak],
                  &inp[(size_t)(row0 + lar) * DD + k0 + lak]);
            cpa16(&sB[buf ^ 1][lbk * BSTR + lbn],
                  &W[(size_t)(k0 + lbk) * MM + col0 + lbn]);
            cpa_commit();
            cpa_wait1();
        } else {
            cpa_wait0();
        }
        __syncthreads();

        #pragma unroll
        for (int ks = 0; ks < 2; ks++) {
            const int k8 = ks * 8;
            unsigned am[2][4];
            #pragma unroll
            for (int mt = 0; mt < 2; mt++) {
                const int rb = (wr * 32 + mt * 16 + gq) * ASTR + k8 + kq;
                am[mt][0] = sA[buf][rb];        am[mt][1] = sA[buf][rb + 8 * ASTR];
                am[mt][2] = sA[buf][rb + 4];    am[mt][3] = sA[buf][rb + 8 * ASTR + 4];
            }
            #pragma unroll
            for (int nt = 0; nt < 2; nt++) {
                const int nb = wc * 16 + nt * 8 + gq;
                unsigned b[2];
                b[0] = sB[buf][(k8 + kq) * BSTR + nb];
                b[1] = sB[buf][(k8 + kq + 4) * BSTR + nb];
                mma8(acc[0][nt], am[0], b);
                mma8(acc[1][nt], am[1], b);
            }
        }
        __syncthreads();
        buf ^= 1;
    }

    float* outp = g_x + (size_t)z * BB * MM;
    #pragma unroll
    for (int nt = 0; nt < 2; nt++) {
        const int c = col0 + wc * 16 + nt * 8 + 2 * kq;
        float2 bv = make_float2(0.f, 0.f);
        if (z == 0) bv = *(const float2*)&bemb[c];
        #pragma unroll
        for (int mt = 0; mt < 2; mt++) {
            #pragma unroll
            for (int h = 0; h < 2; h++) {
                const int r = row0 + wr * 32 + mt * 16 + gq + h * 8;
                float2 o;
                o.x = acc[mt][nt][2 * h + 0] + bv.x;
                o.y = acc[mt][nt][2 * h + 1] + bv.y;
                *(float2*)&outp[(size_t)r * MM + c] = o;
            }
        }
    }
}

// ---------------------------------------------------------------------------
// Kernel B: attention per (b, h); writes g_mp = m_state + attended.
// ---------------------------------------------------------------------------
__global__ __launch_bounds__(256) void attn_kernel(const float* __restrict__ mstate)
{
    __shared__ __align__(16) float kv[17][HSD];
    __shared__ float sc[16][20];

    const int bh  = blockIdx.x;
    const int b   = bh >> 3;
    const int h   = bh & 7;
    const int tid = threadIdx.x;

    const float* mb = mstate + (size_t)b * SS * MM + h * HSD;

    for (int i = tid; i < 17 * HSD; i += 256) {
        int t = i >> 7, d = i & 127;
        kv[t][d] = (t < SS) ? mb[(size_t)t * MM + d]
                            : g_x[(size_t)b * MM + h * HSD + d];
    }
    __syncthreads();

    const int wid = tid >> 5, lane = tid & 31;
    for (int s = wid; s < 16; s += 8) {
        for (int t = 0; t < 17; t++) {
            float sum = 0.f;
            #pragma unroll
            for (int d = lane; d < HSD; d += 32) sum += kv[s][d] * kv[t][d];
            #pragma unroll
            for (int o = 16; o; o >>= 1) sum += __shfl_xor_sync(0xffffffffu, sum, o);
            if (lane == 0) sc[s][t] = sum * 0.08838834764831845f;
        }
    }
    __syncthreads();

    if (tid < 16) {
        float mx = sc[tid][0];
        for (int t = 1; t < 17; t++) mx = fmaxf(mx, sc[tid][t]);
        float sum = 0.f;
        for (int t = 0; t < 17; t++) { float e = expf(sc[tid][t] - mx); sc[tid][t] = e; sum += e; }
        float inv = 1.0f / sum;
        for (int t = 0; t < 17; t++) sc[tid][t] *= inv;
    }
    __syncthreads();

    for (int i = tid; i < SS * HSD; i += 256) {
        int s = i >> 7, d = i & 127;
        float acc = 0.f;
        #pragma unroll
        for (int t = 0; t < 17; t++) acc += sc[s][t] * kv[t][d];
        g_mp[((size_t)b * SS + s) * MM + h * HSD + d] = kv[s][d] + acc;
    }
}

// ---------------------------------------------------------------------------
// Kernel C: fused 4-way tf32-mma GEMM + gate epilogue. 2-stage cp.async.
// Dynamic smem: [2 stages][ sAm(AW) | sAh(AW) | sB[4](BW each) ]
// ---------------------------------------------------------------------------
#define STAGE_W (2 * AW + 4 * BW)         // words per stage = 2560+4608 = 7168
#define SMEM_BYTES (2 * STAGE_W * 4)      // 57344 bytes

__global__ __launch_bounds__(256) void fused_gate_mma(
    const float* __restrict__ hstate, const float* __restrict__ mstate,
    const float* __restrict__ Wg,  const float* __restrict__ bg,
    const float* __restrict__ Wuf, const float* __restrict__ buf_,
    const float* __restrict__ Wui, const float* __restrict__ bui,
    const float* __restrict__ Wuo, const float* __restrict__ buo,
    float* __restrict__ out)
{
    extern __shared__ unsigned smem_raw[];

    const int tid  = threadIdx.x;
    const int lane = tid & 31, wid = tid >> 5;
    const int wr = wid >> 2, wc = wid & 3;
    const int row0 = blockIdx.y * 64, col0 = blockIdx.x * 64;

    const int lar = tid >> 2;
    const int lak = (tid & 3) * 4;
    const int lbk = tid >> 4;
    const int lbn = (tid & 15) * 4;
    const int kq = lane & 3, gq = lane >> 2;

    const float* Bp[4] = { Wg, Wuf, Wui, Wuo };

    // per-stage pointers
    unsigned* sAm[2]; unsigned* sAh[2]; unsigned* sB[2][4];
    #pragma unroll
    for (int s = 0; s < 2; s++) {
        unsigned* base = smem_raw + s * STAGE_W;
        sAm[s] = base;
        sAh[s] = base + AW;
        #pragma unroll
        for (int g = 0; g < 4; g++) sB[s][g] = base + 2 * AW + g * BW;
    }

    // stage 0 loads
    {
        const size_t aoff = (size_t)(row0 + lar) * MM + lak;
        cpa16(&sAm[0][lar * ASTR + lak], &g_mp[aoff]);
        cpa16(&sAh[0][lar * ASTR + lak], &hstate[aoff]);
        const size_t boff = (size_t)lbk * MM + col0 + lbn;
        #pragma unroll
        for (int g = 0; g < 4; g++)
            cpa16(&sB[0][g][lbk * BSTR + lbn], &Bp[g][boff]);
        cpa_commit();
    }

    float acc[4][2][2][4] = {};   // [gemm][mt][nt][reg]
    int buf = 0;

    for (int kt = 0; kt < MM / 16; kt++) {
        if (kt + 1 < MM / 16) {
            const int k0 = (kt + 1) * 16;
            const size_t aoff = (size_t)(row0 + lar) * MM + k0 + lak;
            cpa16(&sAm[buf ^ 1][lar * ASTR + lak], &g_mp[aoff]);
            cpa16(&sAh[buf ^ 1][lar * ASTR + lak], &hstate[aoff]);
            const size_t boff = (size_t)(k0 + lbk) * MM + col0 + lbn;
            #pragma unroll
            for (int g = 0; g < 4; g++)
                cpa16(&sB[buf ^ 1][g][lbk * BSTR + lbn], &Bp[g][boff]);
            cpa_commit();
            cpa_wait1();
        } else {
            cpa_wait0();
        }
        __syncthreads();

        #pragma unroll
        for (int ks = 0; ks < 2; ks++) {
            const int k8 = ks * 8;
            unsigned am[2][4], ah[2][4];
            #pragma unroll
            for (int mt = 0; mt < 2; mt++) {
                const int rb = (wr * 32 + mt * 16 + gq) * ASTR + k8 + kq;
                am[mt][0] = sAm[buf][rb];       am[mt][1] = sAm[buf][rb + 8 * ASTR];
                am[mt][2] = sAm[buf][rb + 4];   am[mt][3] = sAm[buf][rb + 8 * ASTR + 4];
                ah[mt][0] = sAh[buf][rb];       ah[mt][1] = sAh[buf][rb + 8 * ASTR];
                ah[mt][2] = sAh[buf][rb + 4];   ah[mt][3] = sAh[buf][rb + 8 * ASTR + 4];
            }
            #pragma unroll
            for (int nt = 0; nt < 2; nt++) {
                const int nb = wc * 16 + nt * 8 + gq;
                #pragma unroll
                for (int g = 0; g < 4; g++) {
                    unsigned b[2];
                    b[0] = sB[buf][g][(k8 + kq) * BSTR + nb];
                    b[1] = sB[buf][g][(k8 + kq + 4) * BSTR + nb];
                    if (g == 0) {
                        mma8(acc[0][0][nt], am[0], b);
                        mma8(acc[0][1][nt], am[1], b);
                    } else {
                        mma8(acc[g][0][nt], ah[0], b);
                        mma8(acc[g][1][nt], ah[1], b);
                    }
                }
            }
        }
        __syncthreads();
        buf ^= 1;
    }

    // -------- fused gate epilogue --------
    #pragma unroll
    for (int nt = 0; nt < 2; nt++) {
        const int c = col0 + wc * 16 + nt * 8 + 2 * kq;
        const float2 bgv = *(const float2*)&bg[c];
        const float2 bfv = *(const float2*)&buf_[c];
        const float2 biv = *(const float2*)&bui[c];
        const float2 bov = *(const float2*)&buo[c];
        #pragma unroll
        for (int mt = 0; mt < 2; mt++) {
            #pragma unroll
            for (int h = 0; h < 2; h++) {
                const int r = row0 + wr * 32 + mt * 16 + gq + h * 8;
                const int bidx = r >> 4;
                const size_t base = (size_t)r * MM + c;
                const float2 mv  = *(const float2*)&mstate[base];
                const float2 mpv = *(const float2*)&g_mp[base];
                const float2 wfv = *(const float2*)&g_x[(size_t)1 * BB * MM + (size_t)bidx * MM + c];
                const float2 wiv = *(const float2*)&g_x[(size_t)2 * BB * MM + (size_t)bidx * MM + c];
                const float2 wov = *(const float2*)&g_x[(size_t)3 * BB * MM + (size_t)bidx * MM + c];

                float2 nm, nh;
                {
                    const float mpf = acc[0][mt][nt][2 * h + 0] + bgv.x + mpv.x;
                    const float fgt = sigf(acc[1][mt][nt][2 * h + 0] + bfv.x + wfv.x);
                    const float igt = sigf(acc[2][mt][nt][2 * h + 0] + biv.x + wiv.x);
                    const float ogt = sigf(acc[3][mt][nt][2 * h + 0] + bov.x + wov.x);
                    nm.x = sigf(mv.x * fgt + 1.0f) + mpf * sigf(igt);
                    nh.x = tanhf(mv.x) * sigf(ogt);
                }
                {
                    const float mpf = acc[0][mt][nt][2 * h + 1] + bgv.y + mpv.y;
                    const float fgt = sigf(acc[1][mt][nt][2 * h + 1] + bfv.y + wfv.y);
                    const float igt = sigf(acc[2][mt][nt][2 * h + 1] + biv.y + wiv.y);
                    const float ogt = sigf(acc[3][mt][nt][2 * h + 1] + bov.y + wov.y);
                    nm.y = sigf(mv.y * fgt + 1.0f) + mpf * sigf(igt);
                    nh.y = tanhf(mv.y) * sigf(ogt);
                }
                *(float2*)&out[base]        = nm;
                *(float2*)&out[BSMN + base] = nh;
            }
        }
    }
}

// ---------------------------------------------------------------------------
extern "C" void kernel_launch(void* const* d_in, const int* in_sizes, int n_in,
                              void* d_out, int out_size)
{
    const float* inputs  = (const float*)d_in[0];
    const float* h_state = (const float*)d_in[1];
    const float* m_state = (const float*)d_in[2];
    const float* W_emb   = (const float*)d_in[3];
    const float* b_emb   = (const float*)d_in[4];
    const float* W_g     = (const float*)d_in[5];
    const float* b_g     = (const float*)d_in[6];
    const float* W_wf    = (const float*)d_in[7];
    const float* W_wi    = (const float*)d_in[8];
    const float* W_wo    = (const float*)d_in[9];
    const float* W_uf    = (const float*)d_in[10];
    const float* b_uf    = (const float*)d_in[11];
    const float* W_ui    = (const float*)d_in[12];
    const float* b_ui    = (const float*)d_in[13];
    const float* W_uo    = (const float*)d_in[14];
    const float* b_uo    = (const float*)d_in[15];
    float* out = (float*)d_out;

    cudaFuncSetAttribute(fused_gate_mma,
                         cudaFuncAttributeMaxDynamicSharedMemorySize, SMEM_BYTES);

    gemm_x_mma<<<dim3(16, 4, 4), 256>>>(inputs, W_emb, W_wf, W_wi, W_wo, b_emb);
    attn_kernel<<<BB * HH, 256>>>(m_state);
    fused_gate_mma<<<dim3(16, 64), 256, SMEM_BYTES>>>(h_state, m_state,
                                                      W_g, b_g, W_uf, b_uf,
                                                      W_ui, b_ui, W_uo, b_uo, out);
}

// round 5
// speedup vs baseline: 2.9064x; 1.3472x over previous
#include <cuda_runtime.h>
#include <math.h>
#include <stdint.h>

// Problem dims
#define BB   256
#define SS   16
#define HH   8
#define HSD  128
#define DD   1024
#define MM   1024
#define BSR  (BB*SS)
#define BSMN ((size_t)BSR*MM)

// Scratch (__device__ globals; no allocs allowed)
__device__ float g_x[4 * BB * MM];          // [4][B][M]: x_emb, wx_f, wx_i, wx_o
__device__ float g_mp[BSR * MM];            // m_state + attended
__device__ float g_acc[4][BSR * MM];        // raw GEMM results: g, f, i, o

__device__ __forceinline__ float sigf(float x) { return 1.0f / (1.0f + expf(-x)); }

// Raw fp32 bits fed to tf32 MMA (HW reads top 19 bits => RZ-truncated tf32).
__device__ __forceinline__ void mma8(float* c, const unsigned* a, const unsigned* b) {
    asm volatile(
        "mma.sync.aligned.m16n8k8.row.col.f32.tf32.tf32.f32 "
        "{%0,%1,%2,%3}, {%4,%5,%6,%7}, {%8,%9}, {%0,%1,%2,%3};"
        : "+f"(c[0]), "+f"(c[1]), "+f"(c[2]), "+f"(c[3])
        : "r"(a[0]), "r"(a[1]), "r"(a[2]), "r"(a[3]), "r"(b[0]), "r"(b[1]));
}

__device__ __forceinline__ void cpa16(void* dst, const void* src) {
    unsigned s = (unsigned)__cvta_generic_to_shared(dst);
    asm volatile("cp.async.cg.shared.global [%0], [%1], 16;" :: "r"(s), "l"(src));
}
__device__ __forceinline__ void cpa_commit() { asm volatile("cp.async.commit_group;"); }
__device__ __forceinline__ void cpa_wait0()  { asm volatile("cp.async.wait_group 0;"); }
__device__ __forceinline__ void cpa_wait1()  { asm volatile("cp.async.wait_group 1;"); }

// ---------------------------------------------------------------------------
// Kernel A: X[z] = inputs @ W[z] (+ b_emb for z==0). BM=64,BN=64,BK=16.
// ---------------------------------------------------------------------------
#define ASTR0 20
#define BSTR0 72
#define AW0   (64 * ASTR0)
#define BW0   (16 * BSTR0)

__global__ __launch_bounds__(256) void gemm_x_mma(
    const float* __restrict__ inp,  const float* __restrict__ Wemb,
    const float* __restrict__ Wwf,  const float* __restrict__ Wwi,
    const float* __restrict__ Wwo,  const float* __restrict__ bemb)
{
    __shared__ unsigned sA[2][AW0];
    __shared__ unsigned sB[2][BW0];

    const int z = blockIdx.z;
    const float* W = (z == 0) ? Wemb : (z == 1) ? Wwf : (z == 2) ? Wwi : Wwo;

    const int tid  = threadIdx.x;
    const int lane = tid & 31, wid = tid >> 5;
    const int wr = wid >> 2, wc = wid & 3;
    const int row0 = blockIdx.y * 64, col0 = blockIdx.x * 64;

    const int lar = tid >> 2;
    const int lak = (tid & 3) * 4;
    const int lbk = tid >> 4;
    const int lbn = (tid & 15) * 4;
    const int kq = lane & 3, gq = lane >> 2;

    cpa16(&sA[0][lar * ASTR0 + lak], &inp[(size_t)(row0 + lar) * DD + lak]);
    cpa16(&sB[0][lbk * BSTR0 + lbn], &W[(size_t)lbk * MM + col0 + lbn]);
    cpa_commit();

    float acc[2][2][4] = {};
    int buf = 0;

    for (int kt = 0; kt < DD / 16; kt++) {
        if (kt + 1 < DD / 16) {
            const int k0 = (kt + 1) * 16;
            cpa16(&sA[buf ^ 1][lar * ASTR0 + lak],
                  &inp[(size_t)(row0 + lar) * DD + k0 + lak]);
            cpa16(&sB[buf ^ 1][lbk * BSTR0 + lbn],
                  &W[(size_t)(k0 + lbk) * MM + col0 + lbn]);
            cpa_commit();
            cpa_wait1();
        } else {
            cpa_wait0();
        }
        __syncthreads();

        #pragma unroll
        for (int ks = 0; ks < 2; ks++) {
            const int k8 = ks * 8;
            unsigned am[2][4];
            #pragma unroll
            for (int mt = 0; mt < 2; mt++) {
                const int rb = (wr * 32 + mt * 16 + gq) * ASTR0 + k8 + kq;
                am[mt][0] = sA[buf][rb];        am[mt][1] = sA[buf][rb + 8 * ASTR0];
                am[mt][2] = sA[buf][rb + 4];    am[mt][3] = sA[buf][rb + 8 * ASTR0 + 4];
            }
            #pragma unroll
            for (int nt = 0; nt < 2; nt++) {
                const int nb = wc * 16 + nt * 8 + gq;
                unsigned b[2];
                b[0] = sB[buf][(k8 + kq) * BSTR0 + nb];
                b[1] = sB[buf][(k8 + kq + 4) * BSTR0 + nb];
                mma8(acc[0][nt], am[0], b);
                mma8(acc[1][nt], am[1], b);
            }
        }
        __syncthreads();
        buf ^= 1;
    }

    float* outp = g_x + (size_t)z * BB * MM;
    #pragma unroll
    for (int nt = 0; nt < 2; nt++) {
        const int c = col0 + wc * 16 + nt * 8 + 2 * kq;
        float2 bv = make_float2(0.f, 0.f);
        if (z == 0) bv = *(const float2*)&bemb[c];
        #pragma unroll
        for (int mt = 0; mt < 2; mt++) {
            #pragma unroll
            for (int h = 0; h < 2; h++) {
                const int r = row0 + wr * 32 + mt * 16 + gq + h * 8;
                float2 o;
                o.x = acc[mt][nt][2 * h + 0] + bv.x;
                o.y = acc[mt][nt][2 * h + 1] + bv.y;
                *(float2*)&outp[(size_t)r * MM + c] = o;
            }
        }
    }
}

// ---------------------------------------------------------------------------
// Kernel B: attention per (b, h); writes g_mp = m_state + attended.
// ---------------------------------------------------------------------------
__global__ __launch_bounds__(256) void attn_kernel(const float* __restrict__ mstate)
{
    __shared__ __align__(16) float kv[17][HSD];
    __shared__ float sc[16][20];

    const int bh  = blockIdx.x;
    const int b   = bh >> 3;
    const int h   = bh & 7;
    const int tid = threadIdx.x;

    const float* mb = mstate + (size_t)b * SS * MM + h * HSD;

    for (int i = tid; i < 17 * HSD; i += 256) {
        int t = i >> 7, d = i & 127;
        kv[t][d] = (t < SS) ? mb[(size_t)t * MM + d]
                            : g_x[(size_t)b * MM + h * HSD + d];
    }
    __syncthreads();

    const int wid = tid >> 5, lane = tid & 31;
    for (int s = wid; s < 16; s += 8) {
        for (int t = 0; t < 17; t++) {
            float sum = 0.f;
            #pragma unroll
            for (int d = lane; d < HSD; d += 32) sum += kv[s][d] * kv[t][d];
            #pragma unroll
            for (int o = 16; o; o >>= 1) sum += __shfl_xor_sync(0xffffffffu, sum, o);
            if (lane == 0) sc[s][t] = sum * 0.08838834764831845f;
        }
    }
    __syncthreads();

    if (tid < 16) {
        float mx = sc[tid][0];
        for (int t = 1; t < 17; t++) mx = fmaxf(mx, sc[tid][t]);
        float sum = 0.f;
        for (int t = 0; t < 17; t++) { float e = expf(sc[tid][t] - mx); sc[tid][t] = e; sum += e; }
        float inv = 1.0f / sum;
        for (int t = 0; t < 17; t++) sc[tid][t] *= inv;
    }
    __syncthreads();

    for (int i = tid; i < SS * HSD; i += 256) {
        int s = i >> 7, d = i & 127;
        float acc = 0.f;
        #pragma unroll
        for (int t = 0; t < 17; t++) acc += sc[s][t] * kv[t][d];
        g_mp[((size_t)b * SS + s) * MM + h * HSD + d] = kv[s][d] + acc;
    }
}

// ---------------------------------------------------------------------------
// Kernel C: big tf32 GEMM, BM=128, BN=128, BK=16, 256 thr, warp tile 64x32.
// z selects: 0: g_mp @ Wg ; 1..3: hstate @ Wu{f,i,o}. Writes g_acc[z] raw.
// A smem [m][k] stride 20; B smem [k][n] stride 136. Both conflict-free.
// ---------------------------------------------------------------------------
#define ASTR 20
#define BSTR 136
#define AWW  (128 * ASTR)    // 2560 words
#define BWW  (16 * BSTR)     // 2176 words

__global__ __launch_bounds__(256, 2) void big_gemm(
    const float* __restrict__ hstate,
    const float* __restrict__ Wg,  const float* __restrict__ Wuf,
    const float* __restrict__ Wui, const float* __restrict__ Wuo)
{
    __shared__ unsigned sA[2][AWW];
    __shared__ unsigned sB[2][BWW];

    const int z = blockIdx.z;
    const float* A = (z == 0) ? g_mp : hstate;
    const float* W = (z == 0) ? Wg : (z == 1) ? Wuf : (z == 2) ? Wui : Wuo;

    const int tid  = threadIdx.x;
    const int lane = tid & 31, wid = tid >> 5;
    const int wr = wid >> 2;            // 0..1 : 64-row slab
    const int wc = wid & 3;             // 0..3 : 32-col slab
    const int row0 = blockIdx.y * 128, col0 = blockIdx.x * 128;
    const int kq = lane & 3, gq = lane >> 2;

    // A loads: 128 rows x 16 floats = 512 chunks of 16B -> 2/thread
    const int ar0 = tid >> 2;              // chunk i=0: rows 0..63
    const int ac  = (tid & 3) * 4;
    // B loads: 16 rows x 128 floats = 512 chunks -> 2/thread
    const int br0 = tid >> 5;              // chunk i=0: rows 0..7
    const int bc  = (tid & 31) * 4;

    {
        cpa16(&sA[0][ar0 * ASTR + ac],        &A[(size_t)(row0 + ar0) * MM + ac]);
        cpa16(&sA[0][(ar0 + 64) * ASTR + ac], &A[(size_t)(row0 + ar0 + 64) * MM + ac]);
        cpa16(&sB[0][br0 * BSTR + bc],        &W[(size_t)br0 * MM + col0 + bc]);
        cpa16(&sB[0][(br0 + 8) * BSTR + bc],  &W[(size_t)(br0 + 8) * MM + col0 + bc]);
        cpa_commit();
    }

    float acc[4][4][4] = {};   // [mt][nt][reg]
    int buf = 0;

    for (int kt = 0; kt < MM / 16; kt++) {
        if (kt + 1 < MM / 16) {
            const int k0 = (kt + 1) * 16;
            cpa16(&sA[buf ^ 1][ar0 * ASTR + ac],
                  &A[(size_t)(row0 + ar0) * MM + k0 + ac]);
            cpa16(&sA[buf ^ 1][(ar0 + 64) * ASTR + ac],
                  &A[(size_t)(row0 + ar0 + 64) * MM + k0 + ac]);
            cpa16(&sB[buf ^ 1][br0 * BSTR + bc],
                  &W[(size_t)(k0 + br0) * MM + col0 + bc]);
            cpa16(&sB[buf ^ 1][(br0 + 8) * BSTR + bc],
                  &W[(size_t)(k0 + br0 + 8) * MM + col0 + bc]);
            cpa_commit();
            cpa_wait1();
        } else {
            cpa_wait0();
        }
        __syncthreads();

        #pragma unroll
        for (int ks = 0; ks < 2; ks++) {
            const int k8 = ks * 8;
            unsigned am[4][4];
            #pragma unroll
            for (int mt = 0; mt < 4; mt++) {
                const int rb = (wr * 64 + mt * 16 + gq) * ASTR + k8 + kq;
                am[mt][0] = sA[buf][rb];
                am[mt][1] = sA[buf][rb + 8 * ASTR];
                am[mt][2] = sA[buf][rb + 4];
                am[mt][3] = sA[buf][rb + 8 * ASTR + 4];
            }
            #pragma unroll
            for (int nt = 0; nt < 4; nt++) {
                const int nb = wc * 32 + nt * 8 + gq;
                unsigned b[2];
                b[0] = sB[buf][(k8 + kq) * BSTR + nb];
                b[1] = sB[buf][(k8 + kq + 4) * BSTR + nb];
                #pragma unroll
                for (int mt = 0; mt < 4; mt++)
                    mma8(acc[mt][nt], am[mt], b);
            }
        }
        __syncthreads();
        buf ^= 1;
    }

    float* outp = g_acc[z];
    #pragma unroll
    for (int nt = 0; nt < 4; nt++) {
        const int c = col0 + wc * 32 + nt * 8 + 2 * kq;
        #pragma unroll
        for (int mt = 0; mt < 4; mt++) {
            #pragma unroll
            for (int h = 0; h < 2; h++) {
                const int r = row0 + wr * 64 + mt * 16 + gq + h * 8;
                float2 o;
                o.x = acc[mt][nt][2 * h + 0];
                o.y = acc[mt][nt][2 * h + 1];
                *(float2*)&outp[(size_t)r * MM + c] = o;
            }
        }
    }
}

// ---------------------------------------------------------------------------
// Kernel D: streaming gate epilogue. One float4 per thread.
// ---------------------------------------------------------------------------
__global__ __launch_bounds__(256) void gate_epilogue(
    const float* __restrict__ mstate,
    const float* __restrict__ bg,  const float* __restrict__ buf_,
    const float* __restrict__ bui, const float* __restrict__ buo,
    float* __restrict__ out)
{
    const size_t e = ((size_t)blockIdx.x * 256 + threadIdx.x) * 4;
    const int r = (int)(e >> 10);
    const int c = (int)(e & 1023);
    const int bidx = r >> 4;

    const float4 vg  = *(const float4*)&g_acc[0][e];
    const float4 vf  = *(const float4*)&g_acc[1][e];
    const float4 vi  = *(const float4*)&g_acc[2][e];
    const float4 vo  = *(const float4*)&g_acc[3][e];
    const float4 mv  = *(const float4*)&mstate[e];
    const float4 mpv = *(const float4*)&g_mp[e];
    const float4 wfv = *(const float4*)&g_x[(size_t)1 * BB * MM + (size_t)bidx * MM + c];
    const float4 wiv = *(const float4*)&g_x[(size_t)2 * BB * MM + (size_t)bidx * MM + c];
    const float4 wov = *(const float4*)&g_x[(size_t)3 * BB * MM + (size_t)bidx * MM + c];
    const float4 bgv = *(const float4*)&bg[c];
    const float4 bfv = *(const float4*)&buf_[c];
    const float4 biv = *(const float4*)&bui[c];
    const float4 bov = *(const float4*)&buo[c];

    float nm[4], nh[4];
    const float* vgp = &vg.x;  const float* vfp = &vf.x;
    const float* vip = &vi.x;  const float* vop = &vo.x;
    const float* mvp = &mv.x;  const float* mpp = &mpv.x;
    const float* wfp = &wfv.x; const float* wip = &wiv.x; const float* wop = &wov.x;
    const float* bgp = &bgv.x; const float* bfp = &bfv.x;
    const float* bip = &biv.x; const float* bop = &bov.x;
    #pragma unroll
    for (int u = 0; u < 4; u++) {
        const float mpf = vgp[u] + bgp[u] + mpp[u];
        const float fgt = sigf(vfp[u] + bfp[u] + wfp[u]);
        const float igt = sigf(vip[u] + bip[u] + wip[u]);
        const float ogt = sigf(vop[u] + bop[u] + wop[u]);
        nm[u] = sigf(mvp[u] * fgt + 1.0f) + mpf * sigf(igt);
        nh[u] = tanhf(mvp[u]) * sigf(ogt);
    }
    *(float4*)&out[e]        = *(float4*)nm;
    *(float4*)&out[BSMN + e] = *(float4*)nh;
}

// ---------------------------------------------------------------------------
extern "C" void kernel_launch(void* const* d_in, const int* in_sizes, int n_in,
                              void* d_out, int out_size)
{
    const float* inputs  = (const float*)d_in[0];
    const float* h_state = (const float*)d_in[1];
    const float* m_state = (const float*)d_in[2];
    const float* W_emb   = (const float*)d_in[3];
    const float* b_emb   = (const float*)d_in[4];
    const float* W_g     = (const float*)d_in[5];
    const float* b_g     = (const float*)d_in[6];
    const float* W_wf    = (const float*)d_in[7];
    const float* W_wi    = (const float*)d_in[8];
    const float* W_wo    = (const float*)d_in[9];
    const float* W_uf    = (const float*)d_in[10];
    const float* b_uf    = (const float*)d_in[11];
    const float* W_ui    = (const float*)d_in[12];
    const float* b_ui    = (const float*)d_in[13];
    const float* W_uo    = (const float*)d_in[14];
    const float* b_uo    = (const float*)d_in[15];
    float* out = (float*)d_out;

    gemm_x_mma<<<dim3(16, 4, 4), 256>>>(inputs, W_emb, W_wf, W_wi, W_wo, b_emb);
    attn_kernel<<<BB * HH, 256>>>(m_state);
    big_gemm<<<dim3(8, 32, 4), 256>>>(h_state, W_g, W_uf, W_ui, W_uo);
    gate_epilogue<<<(BSR * MM) / (256 * 4), 256>>>(m_state, b_g, b_uf, b_ui, b_uo, out);
}